// round 12
// baseline (speedup 1.0000x reference)
#include <cuda_runtime.h>
#include <math.h>
#include <stdint.h>

#define B     2048
#define T     64
#define D     15
#define H     256
#define G3H   768
#define BC    32            // batch rows per GRU block
#define NBLK  (B / BC)      // 64 blocks per GRU
#define KT    8             // k rows per streamed tile
#define NT    (H / KT)      // 32 tiles per step (Whh only)
#define HPITCH 34           // padded row dim of transposed hT
#define TILE_F (KT * G3H)   // 6144 floats = 24576 bytes per tile

typedef unsigned long long ull;

// ---------------- scratch (static device arrays; no allocation) -------------
__device__ float g_wt[2][H * G3H];     // pre-transposed Whh^T  [k][j]
__device__ float g_h [2][B * H];
__device__ float g_x [2][B * 272];
__device__ float g_a1[2][B * 1024];
__device__ float g_a2[2][B * 1024];
__device__ float g_a3[2][B * 512];
__device__ float g_a4[2][B * 256];

// ---------------- f32x2 helpers ---------------------------------------------
__device__ __forceinline__ void fma2(ull& acc, ull a, ull b) {
    asm("fma.rn.f32x2 %0, %1, %2, %0;" : "+l"(acc) : "l"(a), "l"(b));
}
__device__ __forceinline__ ull bcast2(float w) {
    ull r; unsigned int u = __float_as_uint(w);
    asm("mov.b64 %0, {%1, %1};" : "=l"(r) : "r"(u));
    return r;
}
__device__ __forceinline__ ull pack2(float a, float b) {
    ull r;
    asm("mov.b64 %0, {%1, %2};" : "=l"(r) : "r"(__float_as_uint(a)), "r"(__float_as_uint(b)));
    return r;
}
__device__ __forceinline__ float2 unpack2(ull v) {
    unsigned int lo, hi;
    asm("mov.b64 {%0, %1}, %2;" : "=r"(lo), "=r"(hi) : "l"(v));
    return make_float2(__uint_as_float(lo), __uint_as_float(hi));
}
__device__ __forceinline__ float sigm(float x) {
    return __fdividef(1.0f, 1.0f + __expf(-x));
}
__device__ __forceinline__ void cpa16(uint32_t sdst, const float* gsrc) {
    asm volatile("cp.async.cg.shared.global [%0], [%1], 16;" :: "r"(sdst), "l"(gsrc));
}

// ---------------- prep: WT[gru][k][j] = Whh[j][k] ----------------------------
__global__ void prep_kernel(const float* __restrict__ Whh0,
                            const float* __restrict__ Whh1)
{
    const int gru = blockIdx.y;
    const float* Whh = gru ? Whh1 : Whh0;
    const int k = blockIdx.x / 3;
    const int j = (blockIdx.x % 3) * 256 + threadIdx.x;
    g_wt[gru][k * G3H + j] = Whh[(size_t)j * H + k];
}

// ---------------- GRU kernel -------------------------------------------------
// Grid: (NBLK, 2). Each block: 32 batch rows, full 64-step recurrence.
// SMEM (bytes):
//   hT     [256][34] f32 @0        34816   (h transposed)
//   wt     4 x 6144  f32 @34816    98304   (cp.async ring of Whh^T tiles)
//   winAll [15][768] f32 @133120   46080   (full Wih transposed)
//   bih    [768]     f32 @179200    3072
//   bhh    [768]     f32 @182272    3072
//   xraw   2x[32][16]f32 @185344    4096   (x_t double buffer)
//   len    [32]      i32 @189440     128
#define GRU_SMEM 189568
#define HT(k, r) hT[(k) * HPITCH + (r)]

__global__ __launch_bounds__(256, 1)
void gru_kernel(const float* __restrict__ state, const int* __restrict__ lengths,
                const float* __restrict__ Wih0, const float* __restrict__ bih0,
                const float* __restrict__ bhh0,
                const float* __restrict__ Wih1, const float* __restrict__ bih1,
                const float* __restrict__ bhh1)
{
    extern __shared__ __align__(16) char sraw[];
    float* hT     = (float*)sraw;
    float* wt     = (float*)(sraw + 34816);
    float* winAll = (float*)(sraw + 133120);
    float* bih_s  = (float*)(sraw + 179200);
    float* bhh_s  = (float*)(sraw + 182272);
    float* xraw   = (float*)(sraw + 185344);
    int*   len_s  = (int*)  (sraw + 189440);

    const int gru = blockIdx.y;
    const float* Wih  = gru ? Wih1 : Wih0;
    const float* bihp = gru ? bih1 : bih0;
    const float* bhhp = gru ? bhh1 : bhh0;
    const float* WTg  = g_wt[gru];

    const int b0  = blockIdx.x * BC;
    const int tid = threadIdx.x;
    const int tx  = tid & 63;          // output-column thread (64)
    const int ty  = tid >> 6;          // row-group thread (4) -> rows 8*ty..8*ty+7

    // ---- init ----
    for (int i = tid; i < H * HPITCH; i += 256) hT[i] = 0.0f;
    for (int i = tid; i < D * G3H; i += 256) {
        int d = i / G3H, j = i - d * G3H;
        winAll[d * G3H + j] = Wih[(size_t)j * D + d];
    }
    for (int i = tid; i < G3H; i += 256) { bih_s[i] = bihp[i]; bhh_s[i] = bhhp[i]; }
    if (tid < BC) len_s[tid] = lengths[b0 + tid];
    __syncthreads();

    const ull* hp64 = (const ull*)hT;            // [k][17] view
    const uint32_t swt = (uint32_t)__cvta_generic_to_shared(wt);

    // ---- prologue: prefetch tiles 0, 1 of the uniform tile stream ----
    #pragma unroll
    for (int g = 0; g < 2; ++g) {
        const float* src = WTg + (size_t)(g & 31) * TILE_F;
        const uint32_t dst = swt + (uint32_t)(g & 3) * (TILE_F * 4);
        #pragma unroll
        for (int q = 0; q < 6; ++q) {
            int off = (q * 256 + tid) * 4;
            cpa16(dst + off * 4, src + off);
        }
        asm volatile("cp.async.commit_group;");
    }

    for (int t = 0; t < T; ++t) {
        // stage x_t into xraw[t&1] (consumed after the post-loop barrier)
        float* xb = xraw + (t & 1) * 512;
        for (int i = tid; i < BC * D; i += 256) {
            int r = i / D, d = i - r * D;
            xb[r * 16 + d] = state[(size_t)(b0 + r) * (T * D) + t * D + d];
        }

        ull acc[4][12];
        #pragma unroll
        for (int p = 0; p < 4; ++p)
            #pragma unroll
            for (int i = 0; i < 12; ++i) acc[p][i] = 0ull;

        for (int kt = 0; kt < NT; ++kt) {
            const int g = t * NT + kt;
            // prefetch tile g+2 (wraps harmlessly past end of stream)
            {
                const int gg = g + 2;
                const float* src = WTg + (size_t)(gg & 31) * TILE_F;
                const uint32_t dst = swt + (uint32_t)(gg & 3) * (TILE_F * 4);
                #pragma unroll
                for (int q = 0; q < 6; ++q) {
                    int off = (q * 256 + tid) * 4;
                    cpa16(dst + off * 4, src + off);
                }
                asm volatile("cp.async.commit_group;");
            }
            asm volatile("cp.async.wait_group 2;" ::: "memory");
            __syncthreads();

            const float* wtile = wt + (g & 3) * TILE_F;
            #pragma unroll
            for (int kk = 0; kk < KT; ++kk) {
                const int k = kt * KT + kk;
                ull w2[12];
                #pragma unroll
                for (int i = 0; i < 12; ++i) w2[i] = bcast2(wtile[kk * G3H + tx + 64 * i]);
                ull h2[4];
                #pragma unroll
                for (int p = 0; p < 4; ++p) h2[p] = hp64[k * (HPITCH / 2) + ty * 4 + p];
                #pragma unroll
                for (int p = 0; p < 4; ++p)
                    #pragma unroll
                    for (int i = 0; i < 12; ++i) fma2(acc[p][i], h2[p], w2[i]);
            }
        }
        __syncthreads();   // all tile computes + xb stores visible

        // x contribution: r,z merged into acc, n kept separate (gin)
        ull gin[4][4];
        #pragma unroll
        for (int p = 0; p < 4; ++p)
            #pragma unroll
            for (int c = 0; c < 4; ++c) gin[p][c] = 0ull;
        #pragma unroll
        for (int d = 0; d < D; ++d) {
            ull x2[4];
            #pragma unroll
            for (int p = 0; p < 4; ++p) {
                const int r0 = ty * 8 + 2 * p;
                x2[p] = pack2(xb[r0 * 16 + d], xb[(r0 + 1) * 16 + d]);
            }
            #pragma unroll
            for (int i = 0; i < 8; ++i) {
                ull wr = bcast2(winAll[d * G3H + tx + 64 * i]);
                #pragma unroll
                for (int p = 0; p < 4; ++p) fma2(acc[p][i], x2[p], wr);
            }
            #pragma unroll
            for (int c = 0; c < 4; ++c) {
                ull wn = bcast2(winAll[d * G3H + 512 + tx + 64 * c]);
                #pragma unroll
                for (int p = 0; p < 4; ++p) fma2(gin[p][c], x2[p], wn);
            }
        }

        // gate update (each thread owns matching r/z/n columns and its own rows)
        #pragma unroll
        for (int p = 0; p < 4; ++p) {
            const int r0 = ty * 8 + 2 * p;
            const bool u0 = t < len_s[r0];
            const bool u1 = t < len_s[r0 + 1];
            #pragma unroll
            for (int c = 0; c < 4; ++c) {
                const int jh = tx + 64 * c;
                float2 ar = unpack2(acc[p][c]);        // gi_r + gh_r (no bias)
                float2 az = unpack2(acc[p][c + 4]);    // gi_z + gh_z (no bias)
                float2 an = unpack2(acc[p][c + 8]);    // gh_n only
                float2 gn = unpack2(gin[p][c]);        // gi_n only
                const float brz_r = bih_s[jh]       + bhh_s[jh];
                const float brz_z = bih_s[jh + 256] + bhh_s[jh + 256];
                const float bn_i  = bih_s[jh + 512];
                const float bn_h  = bhh_s[jh + 512];
                if (u0) {
                    float r = sigm(ar.x + brz_r);
                    float z = sigm(az.x + brz_z);
                    float n = tanhf(gn.x + bn_i + r * (an.x + bn_h));
                    float ho = HT(jh, r0);
                    HT(jh, r0) = (1.0f - z) * n + z * ho;
                }
                if (u1) {
                    float r = sigm(ar.y + brz_r);
                    float z = sigm(az.y + brz_z);
                    float n = tanhf(gn.y + bn_i + r * (an.y + bn_h));
                    float ho = HT(jh, r0 + 1);
                    HT(jh, r0 + 1) = (1.0f - z) * n + z * ho;
                }
            }
        }
        __syncthreads();   // h update visible before next step's tile compute
    }

    asm volatile("cp.async.wait_group 0;" ::: "memory");

    // write final h (coalesced in j)
    for (int e = tid; e < BC * H; e += 256) {
        int r = e >> 8, j = e & 255;
        g_h[gru][(size_t)(b0 + r) * H + j] = HT(j, r);
    }
}

// ---------------- concat: x = [state[:,0,:] | action | h] --------------------
__global__ void concat_kernel(const float* __restrict__ state,
                              const float* __restrict__ action)
{
    const int gru = blockIdx.y;
    const int idx = blockIdx.x * 256 + threadIdx.x;
    if (idx >= B * 272) return;
    const int b = idx / 272, c = idx - b * 272;
    float v;
    if (c < D)       v = state[(size_t)b * T * D + c];
    else if (c == D) v = action[b];
    else             v = g_h[gru][(size_t)b * H + (c - 16)];
    g_x[gru][idx] = v;
}

// ---------------- fused GEMM + bias + relu: C = act(A @ W^T + b) ------------
// Block tile 128(M) x 64(N), 256 threads, thread tile 8x4 via f32x2 row pairs.
// Register-staged double buffer: LDG of tile k+1 overlaps compute of tile k.
#define GM 128
#define GN 64
#define GK 16
#define APITCH 130
#define WPITCH 66

__global__ __launch_bounds__(256)
void gemm_kernel(const float* __restrict__ A0, const float* __restrict__ A1,
                 const float* __restrict__ W0, const float* __restrict__ W1,
                 const float* __restrict__ Bb0, const float* __restrict__ Bb1,
                 float* __restrict__ C0, float* __restrict__ C1,
                 int N, int K, int relu)
{
    __shared__ __align__(16) float AT[2][GK][APITCH];
    __shared__ __align__(16) float WTs[2][GK][WPITCH];

    const int z = blockIdx.z;
    const float* A    = z ? A1  : A0;
    const float* W    = z ? W1  : W0;
    const float* bias = z ? Bb1 : Bb0;
    float* C          = z ? C1  : C0;

    const int n0 = blockIdx.x * GN;
    const int m0 = blockIdx.y * GM;
    const int tid = threadIdx.x;
    const int tx = tid & 15, ty = tid >> 4;

    // staging geometry
    const int ar0 = (tid) >> 2,        ac0 = (tid & 3) << 2;       // q=0
    const int ar1 = (256 + tid) >> 2,  ac1 = ac0;                  // q=1
    const int wn  = tid >> 2,          wc  = (tid & 3) << 2;

    ull acc[4][4];
    #pragma unroll
    for (int p = 0; p < 4; ++p)
        #pragma unroll
        for (int c = 0; c < 4; ++c) acc[p][c] = 0ull;

    const int KTILES = K / GK;
    float4 rA0, rA1, rW;

    rA0 = *(const float4*)(A + (size_t)(m0 + ar0) * K + ac0);
    rA1 = *(const float4*)(A + (size_t)(m0 + ar1) * K + ac1);
    rW  = *(const float4*)(W + (size_t)(n0 + wn)  * K + wc);
    {
        AT[0][ac0 + 0][ar0] = rA0.x; AT[0][ac0 + 1][ar0] = rA0.y;
        AT[0][ac0 + 2][ar0] = rA0.z; AT[0][ac0 + 3][ar0] = rA0.w;
        AT[0][ac1 + 0][ar1] = rA1.x; AT[0][ac1 + 1][ar1] = rA1.y;
        AT[0][ac1 + 2][ar1] = rA1.z; AT[0][ac1 + 3][ar1] = rA1.w;
        WTs[0][wc + 0][wn] = rW.x; WTs[0][wc + 1][wn] = rW.y;
        WTs[0][wc + 2][wn] = rW.z; WTs[0][wc + 3][wn] = rW.w;
    }
    __syncthreads();

    for (int kt = 0; kt < KTILES; ++kt) {
        const int cur = kt & 1;
        const bool more = (kt + 1) < KTILES;
        if (more) {
            const int k0 = (kt + 1) * GK;
            rA0 = *(const float4*)(A + (size_t)(m0 + ar0) * K + k0 + ac0);
            rA1 = *(const float4*)(A + (size_t)(m0 + ar1) * K + k0 + ac1);
            rW  = *(const float4*)(W + (size_t)(n0 + wn)  * K + k0 + wc);
        }
        const ull* at64 = (const ull*)AT[cur];
        #pragma unroll
        for (int kk = 0; kk < GK; ++kk) {
            ull a2[4], w2[4];
            #pragma unroll
            for (int p = 0; p < 4; ++p) a2[p] = at64[kk * (APITCH / 2) + ty * 4 + p];
            #pragma unroll
            for (int c = 0; c < 4; ++c) w2[c] = bcast2(WTs[cur][kk][tx + 16 * c]);
            #pragma unroll
            for (int p = 0; p < 4; ++p)
                #pragma unroll
                for (int c = 0; c < 4; ++c) fma2(acc[p][c], a2[p], w2[c]);
        }
        if (more) {
            const int nb = cur ^ 1;
            AT[nb][ac0 + 0][ar0] = rA0.x; AT[nb][ac0 + 1][ar0] = rA0.y;
            AT[nb][ac0 + 2][ar0] = rA0.z; AT[nb][ac0 + 3][ar0] = rA0.w;
            AT[nb][ac1 + 0][ar1] = rA1.x; AT[nb][ac1 + 1][ar1] = rA1.y;
            AT[nb][ac1 + 2][ar1] = rA1.z; AT[nb][ac1 + 3][ar1] = rA1.w;
            WTs[nb][wc + 0][wn] = rW.x; WTs[nb][wc + 1][wn] = rW.y;
            WTs[nb][wc + 2][wn] = rW.z; WTs[nb][wc + 3][wn] = rW.w;
        }
        __syncthreads();
    }

    #pragma unroll
    for (int c = 0; c < 4; ++c) {
        const int n = n0 + tx + 16 * c;
        const float bv = bias[n];
        #pragma unroll
        for (int p = 0; p < 4; ++p) {
            float2 v = unpack2(acc[p][c]);
            float o0 = v.x + bv, o1 = v.y + bv;
            if (relu) { o0 = fmaxf(o0, 0.0f); o1 = fmaxf(o1, 0.0f); }
            const int r0 = m0 + ty * 8 + 2 * p;
            C[(size_t)r0 * N + n]       = o0;
            C[(size_t)(r0 + 1) * N + n] = o1;
        }
    }
}

// ---------------- final q head: out[b] = a4[b,:] . qw + qb ------------------
__global__ void q_kernel(const float* __restrict__ qw0, const float* __restrict__ qb0,
                         const float* __restrict__ qw1, const float* __restrict__ qb1,
                         float* __restrict__ out)
{
    const int gru = blockIdx.y;
    const float* a4 = g_a4[gru];
    const float* qw = gru ? qw1 : qw0;
    const float  qb = (gru ? qb1 : qb0)[0];
    const int warp = threadIdx.x >> 5, lane = threadIdx.x & 31;
    const int row = blockIdx.x * 8 + warp;
    float sum = 0.0f;
    #pragma unroll
    for (int c = lane; c < 256; c += 32) sum += a4[(size_t)row * 256 + c] * qw[c];
    #pragma unroll
    for (int o = 16; o; o >>= 1) sum += __shfl_xor_sync(0xffffffffu, sum, o);
    if (lane == 0) out[gru * B + row] = sum + qb;
}

// ---------------- launch -----------------------------------------------------
extern "C" void kernel_launch(void* const* d_in, const int* in_sizes, int n_in,
                              void* d_out, int out_size)
{
    const float* state   = (const float*)d_in[0];
    const float* action  = (const float*)d_in[1];
    const int*   lengths = (const int*)  d_in[2];
    const float* g1_Wih  = (const float*)d_in[3];
    const float* g1_Whh  = (const float*)d_in[4];
    const float* g1_bih  = (const float*)d_in[5];
    const float* g1_bhh  = (const float*)d_in[6];
    const float* fc1_1_w = (const float*)d_in[7];
    const float* fc1_1_b = (const float*)d_in[8];
    const float* fc2_1_w = (const float*)d_in[9];
    const float* fc2_1_b = (const float*)d_in[10];
    const float* fc3_1_w = (const float*)d_in[11];
    const float* fc3_1_b = (const float*)d_in[12];
    const float* fc4_1_w = (const float*)d_in[13];
    const float* fc4_1_b = (const float*)d_in[14];
    const float* q_1_w   = (const float*)d_in[15];
    const float* q_1_b   = (const float*)d_in[16];
    const float* g2_Wih  = (const float*)d_in[17];
    const float* g2_Whh  = (const float*)d_in[18];
    const float* g2_bih  = (const float*)d_in[19];
    const float* g2_bhh  = (const float*)d_in[20];
    const float* fc1_2_w = (const float*)d_in[21];
    const float* fc1_2_b = (const float*)d_in[22];
    const float* fc2_2_w = (const float*)d_in[23];
    const float* fc2_2_b = (const float*)d_in[24];
    const float* fc3_2_w = (const float*)d_in[25];
    const float* fc3_2_b = (const float*)d_in[26];
    const float* fc4_2_w = (const float*)d_in[27];
    const float* fc4_2_b = (const float*)d_in[28];
    const float* q_2_w   = (const float*)d_in[29];
    const float* q_2_b   = (const float*)d_in[30];
    float* out = (float*)d_out;

    float *p_x, *p_a1, *p_a2, *p_a3, *p_a4;
    cudaGetSymbolAddress((void**)&p_x,  g_x);
    cudaGetSymbolAddress((void**)&p_a1, g_a1);
    cudaGetSymbolAddress((void**)&p_a2, g_a2);
    cudaGetSymbolAddress((void**)&p_a3, g_a3);
    cudaGetSymbolAddress((void**)&p_a4, g_a4);

    cudaFuncSetAttribute(gru_kernel, cudaFuncAttributeMaxDynamicSharedMemorySize, GRU_SMEM);

    prep_kernel<<<dim3(768, 2), 256>>>(g1_Whh, g2_Whh);

    gru_kernel<<<dim3(NBLK, 2), 256, GRU_SMEM>>>(
        state, lengths,
        g1_Wih, g1_bih, g1_bhh,
        g2_Wih, g2_bih, g2_bhh);

    concat_kernel<<<dim3((B * 272 + 255) / 256, 2), 256>>>(state, action);

    // fc1: [B,272] -> [B,1024]
    gemm_kernel<<<dim3(1024 / GN, B / GM, 2), 256>>>(
        p_x, p_x + (size_t)B * 272,
        fc1_1_w, fc1_2_w, fc1_1_b, fc1_2_b,
        p_a1, p_a1 + (size_t)B * 1024, 1024, 272, 1);
    // fc2: [B,1024] -> [B,1024]
    gemm_kernel<<<dim3(1024 / GN, B / GM, 2), 256>>>(
        p_a1, p_a1 + (size_t)B * 1024,
        fc2_1_w, fc2_2_w, fc2_1_b, fc2_2_b,
        p_a2, p_a2 + (size_t)B * 1024, 1024, 1024, 1);
    // fc3: [B,1024] -> [B,512]
    gemm_kernel<<<dim3(512 / GN, B / GM, 2), 256>>>(
        p_a2, p_a2 + (size_t)B * 1024,
        fc3_1_w, fc3_2_w, fc3_1_b, fc3_2_b,
        p_a3, p_a3 + (size_t)B * 512, 512, 1024, 1);
    // fc4: [B,512] -> [B,256]
    gemm_kernel<<<dim3(256 / GN, B / GM, 2), 256>>>(
        p_a3, p_a3 + (size_t)B * 512,
        fc4_1_w, fc4_2_w, fc4_1_b, fc4_2_b,
        p_a4, p_a4 + (size_t)B * 256, 256, 512, 1);

    q_kernel<<<dim3(B / 8, 2), 256>>>(q_1_w, q_1_b, q_2_w, q_2_b, out);
}

// round 15
// speedup vs baseline: 1.3725x; 1.3725x over previous
#include <cuda_runtime.h>
#include <math.h>
#include <stdint.h>

#define B     2048
#define T     64
#define D     15
#define H     256
#define G3H   768
#define BC    32            // batch rows per GRU block
#define NBLK  (B / BC)      // 64 blocks per GRU
#define KT    8             // k rows per streamed tile
#define NT    (H / KT)      // 32 tiles per step (Whh only)
#define HPITCH 34           // padded row dim of transposed hT
#define TILE_F (KT * G3H)   // 6144 floats = 24576 bytes per tile

typedef unsigned long long ull;

// ---------------- scratch (static device arrays; no allocation) -------------
__device__ float g_wt[2][H * G3H];     // pre-transposed Whh^T  [k][j]
__device__ float g_h [2][B * H];
__device__ float g_x [2][B * 272];
__device__ float g_a1[2][B * 1024];
__device__ float g_a2[2][B * 1024];
__device__ float g_a3[2][B * 512];
__device__ float g_a4[2][B * 256];

// ---------------- f32x2 helpers ---------------------------------------------
__device__ __forceinline__ void fma2(ull& acc, ull a, ull b) {
    asm("fma.rn.f32x2 %0, %1, %2, %0;" : "+l"(acc) : "l"(a), "l"(b));
}
__device__ __forceinline__ ull bcast2(float w) {
    ull r; unsigned int u = __float_as_uint(w);
    asm("mov.b64 %0, {%1, %1};" : "=l"(r) : "r"(u));
    return r;
}
__device__ __forceinline__ ull pack2(float a, float b) {
    ull r;
    asm("mov.b64 %0, {%1, %2};" : "=l"(r) : "r"(__float_as_uint(a)), "r"(__float_as_uint(b)));
    return r;
}
__device__ __forceinline__ float2 unpack2(ull v) {
    unsigned int lo, hi;
    asm("mov.b64 {%0, %1}, %2;" : "=r"(lo), "=r"(hi) : "l"(v));
    return make_float2(__uint_as_float(lo), __uint_as_float(hi));
}
__device__ __forceinline__ float sigm(float x) {
    return __fdividef(1.0f, 1.0f + __expf(-x));
}
__device__ __forceinline__ void cpa16(uint32_t sdst, const float* gsrc) {
    asm volatile("cp.async.cg.shared.global [%0], [%1], 16;" :: "r"(sdst), "l"(gsrc));
}

// ---------------- prep: WT[gru][k][j] = Whh[j][k] ----------------------------
__global__ void prep_kernel(const float* __restrict__ Whh0,
                            const float* __restrict__ Whh1)
{
    const int gru = blockIdx.y;
    const float* Whh = gru ? Whh1 : Whh0;
    const int k = blockIdx.x / 3;
    const int j = (blockIdx.x % 3) * 256 + threadIdx.x;
    g_wt[gru][k * G3H + j] = Whh[(size_t)j * H + k];
}

// ---------------- GRU kernel -------------------------------------------------
// Grid: (NBLK, 2). Each block: 32 batch rows, full 64-step recurrence.
// SMEM (bytes):
//   hT     [256][34] f32 @0        34816   (h transposed)
//   wt     4 x 6144  f32 @34816    98304   (cp.async ring of Whh^T tiles)
//   winAll [15][768] f32 @133120   46080   (full Wih transposed)
//   bih    [768]     f32 @179200    3072
//   bhh    [768]     f32 @182272    3072
//   xraw   2x[32][16]f32 @185344    4096   (x_t double buffer)
//   len    [32]      i32 @189440     128
#define GRU_SMEM 189568
#define HT(k, r) hT[(k) * HPITCH + (r)]

__global__ __launch_bounds__(256, 1)
void gru_kernel(const float* __restrict__ state, const int* __restrict__ lengths,
                const float* __restrict__ Wih0, const float* __restrict__ bih0,
                const float* __restrict__ bhh0,
                const float* __restrict__ Wih1, const float* __restrict__ bih1,
                const float* __restrict__ bhh1)
{
    extern __shared__ __align__(16) char sraw[];
    float* hT     = (float*)sraw;
    float* wt     = (float*)(sraw + 34816);
    float* winAll = (float*)(sraw + 133120);
    float* bih_s  = (float*)(sraw + 179200);
    float* bhh_s  = (float*)(sraw + 182272);
    float* xraw   = (float*)(sraw + 185344);
    int*   len_s  = (int*)  (sraw + 189440);

    const int gru = blockIdx.y;
    const float* Wih  = gru ? Wih1 : Wih0;
    const float* bihp = gru ? bih1 : bih0;
    const float* bhhp = gru ? bhh1 : bhh0;
    const float* WTg  = g_wt[gru];

    const int b0  = blockIdx.x * BC;
    const int tid = threadIdx.x;
    const int tx  = tid & 63;          // output-column thread (64)
    const int ty  = tid >> 6;          // row-group thread (4) -> rows 8*ty..8*ty+7

    // ---- init ----
    for (int i = tid; i < H * HPITCH; i += 256) hT[i] = 0.0f;
    for (int i = tid; i < D * G3H; i += 256) {
        int d = i / G3H, j = i - d * G3H;
        winAll[d * G3H + j] = Wih[(size_t)j * D + d];
    }
    for (int i = tid; i < G3H; i += 256) { bih_s[i] = bihp[i]; bhh_s[i] = bhhp[i]; }
    if (tid < BC) len_s[tid] = lengths[b0 + tid];
    __syncthreads();

    const ull* hp64 = (const ull*)hT;            // [k][17] view
    const uint32_t swt = (uint32_t)__cvta_generic_to_shared(wt);

    // ---- prologue: prefetch tiles 0, 1 of the uniform tile stream ----
    #pragma unroll
    for (int g = 0; g < 2; ++g) {
        const float* src = WTg + (size_t)(g & 31) * TILE_F;
        const uint32_t dst = swt + (uint32_t)(g & 3) * (TILE_F * 4);
        #pragma unroll
        for (int q = 0; q < 6; ++q) {
            int off = (q * 256 + tid) * 4;
            cpa16(dst + off * 4, src + off);
        }
        asm volatile("cp.async.commit_group;");
    }

    for (int t = 0; t < T; ++t) {
        // stage x_t into xraw[t&1] (consumed after the post-loop barrier)
        float* xb = xraw + (t & 1) * 512;
        for (int i = tid; i < BC * D; i += 256) {
            int r = i / D, d = i - r * D;
            xb[r * 16 + d] = state[(size_t)(b0 + r) * (T * D) + t * D + d];
        }

        ull acc[4][12];
        #pragma unroll
        for (int p = 0; p < 4; ++p)
            #pragma unroll
            for (int i = 0; i < 12; ++i) acc[p][i] = 0ull;

        for (int kt = 0; kt < NT; ++kt) {
            const int g = t * NT + kt;
            // prefetch tile g+2 (wraps harmlessly past end of stream)
            {
                const int gg = g + 2;
                const float* src = WTg + (size_t)(gg & 31) * TILE_F;
                const uint32_t dst = swt + (uint32_t)(gg & 3) * (TILE_F * 4);
                #pragma unroll
                for (int q = 0; q < 6; ++q) {
                    int off = (q * 256 + tid) * 4;
                    cpa16(dst + off * 4, src + off);
                }
                asm volatile("cp.async.commit_group;");
            }
            asm volatile("cp.async.wait_group 2;" ::: "memory");
            __syncthreads();

            const float* wtile = wt + (g & 3) * TILE_F;
            #pragma unroll
            for (int kk = 0; kk < KT; ++kk) {
                const int k = kt * KT + kk;
                ull w2[12];
                #pragma unroll
                for (int i = 0; i < 12; ++i) w2[i] = bcast2(wtile[kk * G3H + tx + 64 * i]);
                ull h2[4];
                #pragma unroll
                for (int p = 0; p < 4; ++p) h2[p] = hp64[k * (HPITCH / 2) + ty * 4 + p];
                #pragma unroll
                for (int p = 0; p < 4; ++p)
                    #pragma unroll
                    for (int i = 0; i < 12; ++i) fma2(acc[p][i], h2[p], w2[i]);
            }
        }
        __syncthreads();   // all tile computes + xb stores visible

        // x contribution: r,z merged into acc, n kept separate (gin)
        ull gin[4][4];
        #pragma unroll
        for (int p = 0; p < 4; ++p)
            #pragma unroll
            for (int c = 0; c < 4; ++c) gin[p][c] = 0ull;
        #pragma unroll
        for (int d = 0; d < D; ++d) {
            ull x2[4];
            #pragma unroll
            for (int p = 0; p < 4; ++p) {
                const int r0 = ty * 8 + 2 * p;
                x2[p] = pack2(xb[r0 * 16 + d], xb[(r0 + 1) * 16 + d]);
            }
            #pragma unroll
            for (int i = 0; i < 8; ++i) {
                ull wr = bcast2(winAll[d * G3H + tx + 64 * i]);
                #pragma unroll
                for (int p = 0; p < 4; ++p) fma2(acc[p][i], x2[p], wr);
            }
            #pragma unroll
            for (int c = 0; c < 4; ++c) {
                ull wn = bcast2(winAll[d * G3H + 512 + tx + 64 * c]);
                #pragma unroll
                for (int p = 0; p < 4; ++p) fma2(gin[p][c], x2[p], wn);
            }
        }

        // gate update (each thread owns matching r/z/n columns and its own rows)
        #pragma unroll
        for (int p = 0; p < 4; ++p) {
            const int r0 = ty * 8 + 2 * p;
            const bool u0 = t < len_s[r0];
            const bool u1 = t < len_s[r0 + 1];
            #pragma unroll
            for (int c = 0; c < 4; ++c) {
                const int jh = tx + 64 * c;
                float2 ar = unpack2(acc[p][c]);        // gi_r + gh_r (no bias)
                float2 az = unpack2(acc[p][c + 4]);    // gi_z + gh_z (no bias)
                float2 an = unpack2(acc[p][c + 8]);    // gh_n only
                float2 gn = unpack2(gin[p][c]);        // gi_n only
                const float brz_r = bih_s[jh]       + bhh_s[jh];
                const float brz_z = bih_s[jh + 256] + bhh_s[jh + 256];
                const float bn_i  = bih_s[jh + 512];
                const float bn_h  = bhh_s[jh + 512];
                if (u0) {
                    float r = sigm(ar.x + brz_r);
                    float z = sigm(az.x + brz_z);
                    float n = tanhf(gn.x + bn_i + r * (an.x + bn_h));
                    float ho = HT(jh, r0);
                    HT(jh, r0) = (1.0f - z) * n + z * ho;
                }
                if (u1) {
                    float r = sigm(ar.y + brz_r);
                    float z = sigm(az.y + brz_z);
                    float n = tanhf(gn.y + bn_i + r * (an.y + bn_h));
                    float ho = HT(jh, r0 + 1);
                    HT(jh, r0 + 1) = (1.0f - z) * n + z * ho;
                }
            }
        }
        __syncthreads();   // h update visible before next step's tile compute
    }

    asm volatile("cp.async.wait_group 0;" ::: "memory");

    // write final h (coalesced in j)
    for (int e = tid; e < BC * H; e += 256) {
        int r = e >> 8, j = e & 255;
        g_h[gru][(size_t)(b0 + r) * H + j] = HT(j, r);
    }
}

// ---------------- concat: x = [state[:,0,:] | action | h] --------------------
__global__ void concat_kernel(const float* __restrict__ state,
                              const float* __restrict__ action)
{
    const int gru = blockIdx.y;
    const int idx = blockIdx.x * 256 + threadIdx.x;
    if (idx >= B * 272) return;
    const int b = idx / 272, c = idx - b * 272;
    float v;
    if (c < D)       v = state[(size_t)b * T * D + c];
    else if (c == D) v = action[b];
    else             v = g_h[gru][(size_t)b * H + (c - 16)];
    g_x[gru][idx] = v;
}

// ---------------- fused GEMM + bias + relu: C = act(A @ W^T + b) ------------
// Block tile 128(M) x 64(N), 256 threads, thread tile 8x4 via f32x2 row pairs.
// Register-staged double buffer: LDG of tile k+1 overlaps compute of tile k.
#define GM 128
#define GN 64
#define GK 16
#define APITCH 130
#define WPITCH 66

__global__ __launch_bounds__(256)
void gemm_kernel(const float* __restrict__ A0, const float* __restrict__ A1,
                 const float* __restrict__ W0, const float* __restrict__ W1,
                 const float* __restrict__ Bb0, const float* __restrict__ Bb1,
                 float* __restrict__ C0, float* __restrict__ C1,
                 int N, int K, int relu)
{
    __shared__ __align__(16) float AT[2][GK][APITCH];
    __shared__ __align__(16) float WTs[2][GK][WPITCH];

    const int z = blockIdx.z;
    const float* A    = z ? A1  : A0;
    const float* W    = z ? W1  : W0;
    const float* bias = z ? Bb1 : Bb0;
    float* C          = z ? C1  : C0;

    const int n0 = blockIdx.x * GN;
    const int m0 = blockIdx.y * GM;
    const int tid = threadIdx.x;
    const int tx = tid & 15, ty = tid >> 4;

    // staging geometry
    const int ar0 = (tid) >> 2,        ac0 = (tid & 3) << 2;       // q=0
    const int ar1 = (256 + tid) >> 2,  ac1 = ac0;                  // q=1
    const int wn  = tid >> 2,          wc  = (tid & 3) << 2;

    ull acc[4][4];
    #pragma unroll
    for (int p = 0; p < 4; ++p)
        #pragma unroll
        for (int c = 0; c < 4; ++c) acc[p][c] = 0ull;

    const int KTILES = K / GK;
    float4 rA0, rA1, rW;

    rA0 = *(const float4*)(A + (size_t)(m0 + ar0) * K + ac0);
    rA1 = *(const float4*)(A + (size_t)(m0 + ar1) * K + ac1);
    rW  = *(const float4*)(W + (size_t)(n0 + wn)  * K + wc);
    {
        AT[0][ac0 + 0][ar0] = rA0.x; AT[0][ac0 + 1][ar0] = rA0.y;
        AT[0][ac0 + 2][ar0] = rA0.z; AT[0][ac0 + 3][ar0] = rA0.w;
        AT[0][ac1 + 0][ar1] = rA1.x; AT[0][ac1 + 1][ar1] = rA1.y;
        AT[0][ac1 + 2][ar1] = rA1.z; AT[0][ac1 + 3][ar1] = rA1.w;
        WTs[0][wc + 0][wn] = rW.x; WTs[0][wc + 1][wn] = rW.y;
        WTs[0][wc + 2][wn] = rW.z; WTs[0][wc + 3][wn] = rW.w;
    }
    __syncthreads();

    for (int kt = 0; kt < KTILES; ++kt) {
        const int cur = kt & 1;
        const bool more = (kt + 1) < KTILES;
        if (more) {
            const int k0 = (kt + 1) * GK;
            rA0 = *(const float4*)(A + (size_t)(m0 + ar0) * K + k0 + ac0);
            rA1 = *(const float4*)(A + (size_t)(m0 + ar1) * K + k0 + ac1);
            rW  = *(const float4*)(W + (size_t)(n0 + wn)  * K + k0 + wc);
        }
        const ull* at64 = (const ull*)AT[cur];
        #pragma unroll
        for (int kk = 0; kk < GK; ++kk) {
            ull a2[4], w2[4];
            #pragma unroll
            for (int p = 0; p < 4; ++p) a2[p] = at64[kk * (APITCH / 2) + ty * 4 + p];
            #pragma unroll
            for (int c = 0; c < 4; ++c) w2[c] = bcast2(WTs[cur][kk][tx + 16 * c]);
            #pragma unroll
            for (int p = 0; p < 4; ++p)
                #pragma unroll
                for (int c = 0; c < 4; ++c) fma2(acc[p][c], a2[p], w2[c]);
        }
        if (more) {
            const int nb = cur ^ 1;
            AT[nb][ac0 + 0][ar0] = rA0.x; AT[nb][ac0 + 1][ar0] = rA0.y;
            AT[nb][ac0 + 2][ar0] = rA0.z; AT[nb][ac0 + 3][ar0] = rA0.w;
            AT[nb][ac1 + 0][ar1] = rA1.x; AT[nb][ac1 + 1][ar1] = rA1.y;
            AT[nb][ac1 + 2][ar1] = rA1.z; AT[nb][ac1 + 3][ar1] = rA1.w;
            WTs[nb][wc + 0][wn] = rW.x; WTs[nb][wc + 1][wn] = rW.y;
            WTs[nb][wc + 2][wn] = rW.z; WTs[nb][wc + 3][wn] = rW.w;
        }
        __syncthreads();
    }

    #pragma unroll
    for (int c = 0; c < 4; ++c) {
        const int n = n0 + tx + 16 * c;
        const float bv = bias[n];
        #pragma unroll
        for (int p = 0; p < 4; ++p) {
            float2 v = unpack2(acc[p][c]);
            float o0 = v.x + bv, o1 = v.y + bv;
            if (relu) { o0 = fmaxf(o0, 0.0f); o1 = fmaxf(o1, 0.0f); }
            const int r0 = m0 + ty * 8 + 2 * p;
            C[(size_t)r0 * N + n]       = o0;
            C[(size_t)(r0 + 1) * N + n] = o1;
        }
    }
}

// ---------------- final q head: out[b] = a4[b,:] . qw + qb ------------------
__global__ void q_kernel(const float* __restrict__ qw0, const float* __restrict__ qb0,
                         const float* __restrict__ qw1, const float* __restrict__ qb1,
                         float* __restrict__ out)
{
    const int gru = blockIdx.y;
    const float* a4 = g_a4[gru];
    const float* qw = gru ? qw1 : qw0;
    const float  qb = (gru ? qb1 : qb0)[0];
    const int warp = threadIdx.x >> 5, lane = threadIdx.x & 31;
    const int row = blockIdx.x * 8 + warp;
    float sum = 0.0f;
    #pragma unroll
    for (int c = lane; c < 256; c += 32) sum += a4[(size_t)row * 256 + c] * qw[c];
    #pragma unroll
    for (int o = 16; o; o >>= 1) sum += __shfl_xor_sync(0xffffffffu, sum, o);
    if (lane == 0) out[gru * B + row] = sum + qb;
}

// ---------------- launch -----------------------------------------------------
extern "C" void kernel_launch(void* const* d_in, const int* in_sizes, int n_in,
                              void* d_out, int out_size)
{
    const float* state   = (const float*)d_in[0];
    const float* action  = (const float*)d_in[1];
    const int*   lengths = (const int*)  d_in[2];
    const float* g1_Wih  = (const float*)d_in[3];
    const float* g1_Whh  = (const float*)d_in[4];
    const float* g1_bih  = (const float*)d_in[5];
    const float* g1_bhh  = (const float*)d_in[6];
    const float* fc1_1_w = (const float*)d_in[7];
    const float* fc1_1_b = (const float*)d_in[8];
    const float* fc2_1_w = (const float*)d_in[9];
    const float* fc2_1_b = (const float*)d_in[10];
    const float* fc3_1_w = (const float*)d_in[11];
    const float* fc3_1_b = (const float*)d_in[12];
    const float* fc4_1_w = (const float*)d_in[13];
    const float* fc4_1_b = (const float*)d_in[14];
    const float* q_1_w   = (const float*)d_in[15];
    const float* q_1_b   = (const float*)d_in[16];
    const float* g2_Wih  = (const float*)d_in[17];
    const float* g2_Whh  = (const float*)d_in[18];
    const float* g2_bih  = (const float*)d_in[19];
    const float* g2_bhh  = (const float*)d_in[20];
    const float* fc1_2_w = (const float*)d_in[21];
    const float* fc1_2_b = (const float*)d_in[22];
    const float* fc2_2_w = (const float*)d_in[23];
    const float* fc2_2_b = (const float*)d_in[24];
    const float* fc3_2_w = (const float*)d_in[25];
    const float* fc3_2_b = (const float*)d_in[26];
    const float* fc4_2_w = (const float*)d_in[27];
    const float* fc4_2_b = (const float*)d_in[28];
    const float* q_2_w   = (const float*)d_in[29];
    const float* q_2_b   = (const float*)d_in[30];
    float* out = (float*)d_out;

    float *p_x, *p_a1, *p_a2, *p_a3, *p_a4;
    cudaGetSymbolAddress((void**)&p_x,  g_x);
    cudaGetSymbolAddress((void**)&p_a1, g_a1);
    cudaGetSymbolAddress((void**)&p_a2, g_a2);
    cudaGetSymbolAddress((void**)&p_a3, g_a3);
    cudaGetSymbolAddress((void**)&p_a4, g_a4);

    cudaFuncSetAttribute(gru_kernel, cudaFuncAttributeMaxDynamicSharedMemorySize, GRU_SMEM);

    prep_kernel<<<dim3(768, 2), 256>>>(g1_Whh, g2_Whh);

    gru_kernel<<<dim3(NBLK, 2), 256, GRU_SMEM>>>(
        state, lengths,
        g1_Wih, g1_bih, g1_bhh,
        g2_Wih, g2_bih, g2_bhh);

    concat_kernel<<<dim3((B * 272 + 255) / 256, 2), 256>>>(state, action);

    // fc1: [B,272] -> [B,1024]
    gemm_kernel<<<dim3(1024 / GN, B / GM, 2), 256>>>(
        p_x, p_x + (size_t)B * 272,
        fc1_1_w, fc1_2_w, fc1_1_b, fc1_2_b,
        p_a1, p_a1 + (size_t)B * 1024, 1024, 272, 1);
    // fc2: [B,1024] -> [B,1024]
    gemm_kernel<<<dim3(1024 / GN, B / GM, 2), 256>>>(
        p_a1, p_a1 + (size_t)B * 1024,
        fc2_1_w, fc2_2_w, fc2_1_b, fc2_2_b,
        p_a2, p_a2 + (size_t)B * 1024, 1024, 1024, 1);
    // fc3: [B,1024] -> [B,512]
    gemm_kernel<<<dim3(512 / GN, B / GM, 2), 256>>>(
        p_a2, p_a2 + (size_t)B * 1024,
        fc3_1_w, fc3_2_w, fc3_1_b, fc3_2_b,
        p_a3, p_a3 + (size_t)B * 512, 512, 1024, 1);
    // fc4: [B,512] -> [B,256]
    gemm_kernel<<<dim3(256 / GN, B / GM, 2), 256>>>(
        p_a3, p_a3 + (size_t)B * 512,
        fc4_1_w, fc4_2_w, fc4_1_b, fc4_2_b,
        p_a4, p_a4 + (size_t)B * 256, 256, 512, 1);

    q_kernel<<<dim3(B / 8, 2), 256>>>(q_1_w, q_1_b, q_2_w, q_2_b, out);
}